// round 1
// baseline (speedup 1.0000x reference)
#include <cuda_runtime.h>
#include <math.h>

// Problem constants (fixed-shape problem)
constexpr int N = 50000;
constexpr int E = 800000;

// ---------------------------------------------------------------------------
// Device scratch (allocation-free rule: __device__ globals)
// ---------------------------------------------------------------------------
__device__ __align__(16) float g_nbr [N * 128];   // segment_sum(x[src], dst)
__device__ __align__(16) float g_h   [N * 128];   // GraphConv output (elu)
__device__ __align__(16) float g_z1  [N * 64];    // h @ W1^T
__device__ __align__(16) float g_as1 [N * 8];
__device__ __align__(16) float g_ad1 [N * 8];
__device__ __align__(16) float g_m1  [N * 8];
__device__ __align__(16) float g_den1[N * 8];
__device__ __align__(16) float g_elog1[(size_t)E * 8];
__device__ __align__(16) float g_agg1[N * 64];
__device__ __align__(16) float g_h2  [N * 64];    // elu(GAT1 out)
__device__ __align__(16) float g_z2  [N * 64];
__device__ float g_as2[N];
__device__ float g_ad2[N];
__device__ float g_m2 [N];
__device__ float g_den2[N];
__device__ float g_elog2[E];
__device__ __align__(16) float g_agg2[N * 64];
__device__ float g_gsum[64];
__device__ int   g_is64;   // 1 if edge_index is int64, 0 if int32

// ---------------------------------------------------------------------------
// Helpers
// ---------------------------------------------------------------------------
__device__ __forceinline__ float lrelu(float x) { return x > 0.f ? x : 0.2f * x; }
__device__ __forceinline__ float elu1(float x)  { return x > 0.f ? x : expf(x) - 1.f; }

__device__ __forceinline__ void redAdd4(float* p, float4 v) {
    asm volatile("red.global.add.v4.f32 [%0], {%1,%2,%3,%4};"
                 :: "l"(p), "f"(v.x), "f"(v.y), "f"(v.z), "f"(v.w) : "memory");
}

// float atomic max via signed/unsigned integer monotonicity trick.
// Valid when buffer initialized to -inf (0xff800000).
__device__ __forceinline__ void atomicMaxF(float* addr, float v) {
    if (v >= 0.f) atomicMax((int*)addr, __float_as_int(v));
    else          atomicMin((unsigned int*)addr, __float_as_uint(v));
}

__device__ __forceinline__ int edge_id(const void* ei, long long idx) {
    return g_is64 ? (int)((const long long*)ei)[idx] : ((const int*)ei)[idx];
}
__device__ __forceinline__ int edge_src(const void* ei, int e) { return edge_id(ei, e); }
__device__ __forceinline__ int edge_dst(const void* ei, int e) { return edge_id(ei, (long long)E + e); }

// ---------------------------------------------------------------------------
// dtype detection: int64 edge_index has zero high words (values < 50000)
// ---------------------------------------------------------------------------
__global__ void detect_kernel(const int* ei) {
    __shared__ int any;
    if (threadIdx.x == 0) any = 0;
    __syncthreads();
    for (int i = threadIdx.x; i < 1024; i += blockDim.x)
        if (ei[2 * i + 1] != 0) atomicOr(&any, 1);
    __syncthreads();
    if (threadIdx.x == 0) g_is64 = any ? 0 : 1;
}

// ---------------------------------------------------------------------------
// init: zero accumulators, -inf maxes
// ---------------------------------------------------------------------------
__global__ void init_kernel() {
    int i = blockIdx.x * blockDim.x + threadIdx.x;
    int stride = gridDim.x * blockDim.x;
    const float NEG_INF = __int_as_float(0xff800000);
    for (int t = i; t < N * 128; t += stride) g_nbr[t] = 0.f;
    for (int t = i; t < N * 64;  t += stride) { g_agg1[t] = 0.f; g_agg2[t] = 0.f; }
    for (int t = i; t < N * 8;   t += stride) g_m1[t] = NEG_INF;
    for (int t = i; t < N;       t += stride) g_m2[t] = NEG_INF;
    if (i < 64) g_gsum[i] = 0.f;
}

// ---------------------------------------------------------------------------
// scatter: nbr[dst] += x[src] ; warp per edge, float4 lanes
// ---------------------------------------------------------------------------
__global__ void scatter_x_kernel(const float* __restrict__ x, const void* __restrict__ ei) {
    int wid  = (blockIdx.x * blockDim.x + threadIdx.x) >> 5;
    int lane = threadIdx.x & 31;
    if (wid >= E) return;
    int s = edge_src(ei, wid);
    int d = edge_dst(ei, wid);
    float4 v = *(const float4*)(x + (size_t)s * 128 + lane * 4);
    redAdd4(g_nbr + (size_t)d * 128 + lane * 4, v);
}

// ---------------------------------------------------------------------------
// Tiled SGEMM: C[M,NCOL] = act( A1 @ Wa^T (+ A2 @ Wb^T) + bias )
// W matrices are [NCOL, K] row-major. BM=BN=BK=64, 128 threads, 8x4 micro.
// ---------------------------------------------------------------------------
__global__ void linear_kernel(const float* __restrict__ A1, const float* __restrict__ Wa, int K1,
                              const float* __restrict__ A2, const float* __restrict__ Wb, int K2,
                              const float* __restrict__ bias, float* __restrict__ C,
                              int M, int NCOL, int act)
{
    __shared__ float As[64][65];   // As[m][k]
    __shared__ float Bs[64][65];   // Bs[c][k]
    const int tid  = threadIdx.x;          // 128 threads
    const int row0 = blockIdx.x * 64;
    const int c0   = blockIdx.y * 64;
    const int rowg = tid >> 4;             // 0..7
    const int colg = tid & 15;             // 0..15

    float acc[8][4];
#pragma unroll
    for (int r = 0; r < 8; r++)
#pragma unroll
        for (int j = 0; j < 4; j++) acc[r][j] = 0.f;

    const int nk1 = K1 >> 6;
    const int nk2 = A2 ? (K2 >> 6) : 0;
    for (int t = 0; t < nk1 + nk2; t++) {
        const float* A; const float* W; int K; int kb;
        if (t < nk1) { A = A1; W = Wa; K = K1; kb = t << 6; }
        else         { A = A2; W = Wb; K = K2; kb = (t - nk1) << 6; }
#pragma unroll
        for (int it = 0; it < 8; it++) {
            int idx = tid + it * 128;
            int m   = idx >> 4;
            int k4  = (idx & 15) << 2;
            float4 av = make_float4(0.f, 0.f, 0.f, 0.f);
            if (row0 + m < M) av = *(const float4*)(A + (size_t)(row0 + m) * K + kb + k4);
            As[m][k4] = av.x; As[m][k4 + 1] = av.y; As[m][k4 + 2] = av.z; As[m][k4 + 3] = av.w;
            float4 bv = *(const float4*)(W + (size_t)(c0 + m) * K + kb + k4);
            Bs[m][k4] = bv.x; Bs[m][k4 + 1] = bv.y; Bs[m][k4 + 2] = bv.z; Bs[m][k4 + 3] = bv.w;
        }
        __syncthreads();
#pragma unroll 16
        for (int k = 0; k < 64; k++) {
            float a[8], b[4];
#pragma unroll
            for (int r = 0; r < 8; r++) a[r] = As[rowg * 8 + r][k];
#pragma unroll
            for (int j = 0; j < 4; j++) b[j] = Bs[colg * 4 + j][k];
#pragma unroll
            for (int r = 0; r < 8; r++)
#pragma unroll
                for (int j = 0; j < 4; j++)
                    acc[r][j] = fmaf(a[r], b[j], acc[r][j]);
        }
        __syncthreads();
    }
#pragma unroll
    for (int r = 0; r < 8; r++) {
        int gr = row0 + rowg * 8 + r;
        if (gr >= M) continue;
#pragma unroll
        for (int j = 0; j < 4; j++) {
            int gc = c0 + colg * 4 + j;
            float v = acc[r][j];
            if (bias) v += bias[gc];
            if (act == 1) v = elu1(v);
            C[(size_t)gr * NCOL + gc] = v;
        }
    }
}

// ---------------------------------------------------------------------------
// GAT1 (8 heads, 8 ch) attention coefficients per node
// ---------------------------------------------------------------------------
__global__ void alpha1_kernel(const float* __restrict__ a1s, const float* __restrict__ a1d) {
    int gid = blockIdx.x * blockDim.x + threadIdx.x;
    if (gid >= N * 8) return;
    int i = gid >> 3, h = gid & 7;
    const float4* z = (const float4*)(g_z1 + (size_t)i * 64 + h * 8);
    float4 z0 = z[0], z1 = z[1];
    const float4* s4 = (const float4*)(a1s + h * 8);
    const float4* d4 = (const float4*)(a1d + h * 8);
    float4 s0 = s4[0], s1 = s4[1], d0 = d4[0], d1 = d4[1];
    float as = z0.x*s0.x + z0.y*s0.y + z0.z*s0.z + z0.w*s0.w
             + z1.x*s1.x + z1.y*s1.y + z1.z*s1.z + z1.w*s1.w;
    float ad = z0.x*d0.x + z0.y*d0.y + z0.z*d0.z + z0.w*d0.w
             + z1.x*d1.x + z1.y*d1.y + z1.z*d1.z + z1.w*d1.w;
    g_as1[gid] = as;
    g_ad1[gid] = ad;
}

__global__ void edge_max1(const void* __restrict__ ei) {
    int e = blockIdx.x * blockDim.x + threadIdx.x;
    if (e >= E) return;
    int s = edge_src(ei, e), d = edge_dst(ei, e);
    float4 s0 = ((const float4*)(g_as1 + (size_t)s * 8))[0];
    float4 s1 = ((const float4*)(g_as1 + (size_t)s * 8))[1];
    float4 d0 = ((const float4*)(g_ad1 + (size_t)d * 8))[0];
    float4 d1 = ((const float4*)(g_ad1 + (size_t)d * 8))[1];
    float4 l0 = make_float4(lrelu(s0.x+d0.x), lrelu(s0.y+d0.y), lrelu(s0.z+d0.z), lrelu(s0.w+d0.w));
    float4 l1 = make_float4(lrelu(s1.x+d1.x), lrelu(s1.y+d1.y), lrelu(s1.z+d1.z), lrelu(s1.w+d1.w));
    float4* lp = (float4*)(g_elog1 + (size_t)e * 8);
    lp[0] = l0; lp[1] = l1;
    float* mp = g_m1 + (size_t)d * 8;
    atomicMaxF(mp + 0, l0.x); atomicMaxF(mp + 1, l0.y);
    atomicMaxF(mp + 2, l0.z); atomicMaxF(mp + 3, l0.w);
    atomicMaxF(mp + 4, l1.x); atomicMaxF(mp + 5, l1.y);
    atomicMaxF(mp + 6, l1.z); atomicMaxF(mp + 7, l1.w);
}

// self-loop: finalize max, seed denom with self exp (plain store, pre-PassB)
__global__ void node_self1(const float* a1s_unused) {
    int gid = blockIdx.x * blockDim.x + threadIdx.x;
    if (gid >= N * 8) return;
    float sl = lrelu(g_as1[gid] + g_ad1[gid]);
    float m  = fmaxf(g_m1[gid], sl);
    g_m1[gid]  = m;
    g_den1[gid] = expf(sl - m);
}

__global__ void edge_exp1(const void* __restrict__ ei) {
    int e = blockIdx.x * blockDim.x + threadIdx.x;
    if (e >= E) return;
    int d = edge_dst(ei, e);
    float4* lp = (float4*)(g_elog1 + (size_t)e * 8);
    float4 l0 = lp[0], l1 = lp[1];
    float4 m0 = ((const float4*)(g_m1 + (size_t)d * 8))[0];
    float4 m1v = ((const float4*)(g_m1 + (size_t)d * 8))[1];
    float4 e0 = make_float4(expf(l0.x-m0.x), expf(l0.y-m0.y), expf(l0.z-m0.z), expf(l0.w-m0.w));
    float4 e1 = make_float4(expf(l1.x-m1v.x), expf(l1.y-m1v.y), expf(l1.z-m1v.z), expf(l1.w-m1v.w));
    lp[0] = e0; lp[1] = e1;
    redAdd4(g_den1 + (size_t)d * 8,     e0);
    redAdd4(g_den1 + (size_t)d * 8 + 4, e1);
}

__global__ void edge_agg1(const void* __restrict__ ei) {
    int gid = blockIdx.x * blockDim.x + threadIdx.x;
    if (gid >= E * 16) return;
    int e = gid >> 4, q = gid & 15, h = q >> 1;
    int s = edge_src(ei, e), d = edge_dst(ei, e);
    float w = g_elog1[(size_t)e * 8 + h] / (g_den1[(size_t)d * 8 + h] + 1e-16f);
    float4 z = ((const float4*)(g_z1 + (size_t)s * 64))[q];
    redAdd4(g_agg1 + (size_t)d * 64 + q * 4, make_float4(w*z.x, w*z.y, w*z.z, w*z.w));
}

// h2 = elu(agg1 + self_contribution + b1)
__global__ void h2_kernel(const float* __restrict__ b1) {
    int gid = blockIdx.x * blockDim.x + threadIdx.x;
    if (gid >= N * 16) return;
    int i = gid >> 4, q = gid & 15, h = q >> 1;
    float sl = lrelu(g_as1[(size_t)i * 8 + h] + g_ad1[(size_t)i * 8 + h]);
    float w  = expf(sl - g_m1[(size_t)i * 8 + h]) / (g_den1[(size_t)i * 8 + h] + 1e-16f);
    float4 z = ((const float4*)(g_z1   + (size_t)i * 64))[q];
    float4 a = ((const float4*)(g_agg1 + (size_t)i * 64))[q];
    float4 bb = ((const float4*)b1)[q];
    float4 v = make_float4(a.x + w*z.x + bb.x, a.y + w*z.y + bb.y,
                           a.z + w*z.z + bb.z, a.w + w*z.w + bb.w);
    v.x = elu1(v.x); v.y = elu1(v.y); v.z = elu1(v.z); v.w = elu1(v.w);
    ((float4*)(g_h2 + (size_t)i * 64))[q] = v;
}

// ---------------------------------------------------------------------------
// GAT2 (1 head, 64 ch)
// ---------------------------------------------------------------------------
__global__ void alpha2_kernel(const float* __restrict__ a2s, const float* __restrict__ a2d) {
    int gt = blockIdx.x * blockDim.x + threadIdx.x;
    int w = gt >> 5, lane = gt & 31;
    if (w >= N) return;
    float2 z  = ((const float2*)(g_z2 + (size_t)w * 64))[lane];
    float2 cs = ((const float2*)a2s)[lane];
    float2 cd = ((const float2*)a2d)[lane];
    float vs = z.x*cs.x + z.y*cs.y;
    float vd = z.x*cd.x + z.y*cd.y;
#pragma unroll
    for (int o = 16; o; o >>= 1) {
        vs += __shfl_down_sync(0xffffffff, vs, o);
        vd += __shfl_down_sync(0xffffffff, vd, o);
    }
    if (lane == 0) { g_as2[w] = vs; g_ad2[w] = vd; }
}

__global__ void edge_max2(const void* __restrict__ ei) {
    int e = blockIdx.x * blockDim.x + threadIdx.x;
    if (e >= E) return;
    int s = edge_src(ei, e), d = edge_dst(ei, e);
    float l = lrelu(g_as2[s] + g_ad2[d]);
    g_elog2[e] = l;
    atomicMaxF(&g_m2[d], l);
}

__global__ void node_self2() {
    int i = blockIdx.x * blockDim.x + threadIdx.x;
    if (i >= N) return;
    float sl = lrelu(g_as2[i] + g_ad2[i]);
    float m  = fmaxf(g_m2[i], sl);
    g_m2[i]  = m;
    g_den2[i] = expf(sl - m);
}

__global__ void edge_exp2(const void* __restrict__ ei) {
    int e = blockIdx.x * blockDim.x + threadIdx.x;
    if (e >= E) return;
    int d = edge_dst(ei, e);
    float ex = expf(g_elog2[e] - g_m2[d]);
    g_elog2[e] = ex;
    atomicAdd(&g_den2[d], ex);
}

__global__ void edge_agg2(const void* __restrict__ ei) {
    int gid = blockIdx.x * blockDim.x + threadIdx.x;
    if (gid >= E * 16) return;
    int e = gid >> 4, q = gid & 15;
    int s = edge_src(ei, e), d = edge_dst(ei, e);
    float w = g_elog2[e] / (g_den2[d] + 1e-16f);
    float4 z = ((const float4*)(g_z2 + (size_t)s * 64))[q];
    redAdd4(g_agg2 + (size_t)d * 64 + q * 4, make_float4(w*z.x, w*z.y, w*z.z, w*z.w));
}

// h3 = agg2 + self + b2; accumulate column sums into g_gsum
__global__ void node_final(const float* __restrict__ b2) {
    __shared__ float4 sm[256];
    int tid = threadIdx.x;          // 256
    int q = tid & 15, r = tid >> 4; // 16 quads x 16 nodes
    int i = blockIdx.x * 16 + r;
    float4 v = make_float4(0.f, 0.f, 0.f, 0.f);
    if (i < N) {
        float sl = lrelu(g_as2[i] + g_ad2[i]);
        float w  = expf(sl - g_m2[i]) / (g_den2[i] + 1e-16f);
        float4 z = ((const float4*)(g_z2   + (size_t)i * 64))[q];
        float4 a = ((const float4*)(g_agg2 + (size_t)i * 64))[q];
        float4 bb = ((const float4*)b2)[q];
        v = make_float4(a.x + w*z.x + bb.x, a.y + w*z.y + bb.y,
                        a.z + w*z.z + bb.z, a.w + w*z.w + bb.w);
    }
    sm[tid] = v;
    __syncthreads();
    if (tid < 16) {
        float4 acc = sm[tid];
        for (int rr = 1; rr < 16; rr++) {
            float4 t = sm[rr * 16 + tid];
            acc.x += t.x; acc.y += t.y; acc.z += t.z; acc.w += t.w;
        }
        atomicAdd(&g_gsum[tid * 4 + 0], acc.x);
        atomicAdd(&g_gsum[tid * 4 + 1], acc.y);
        atomicAdd(&g_gsum[tid * 4 + 2], acc.z);
        atomicAdd(&g_gsum[tid * 4 + 3], acc.w);
    }
}

__global__ void final_kernel(const float* __restrict__ Wr, const float* __restrict__ br,
                             float* __restrict__ out) {
    __shared__ float sm[64];
    int t = threadIdx.x;  // 64
    sm[t] = g_gsum[t] * (1.0f / (float)N) * Wr[t];
    __syncthreads();
    if (t == 0) {
        float s = 0.f;
        for (int i = 0; i < 64; i++) s += sm[i];
        out[0] = s + br[0];
    }
}

// ---------------------------------------------------------------------------
// Launch
// ---------------------------------------------------------------------------
extern "C" void kernel_launch(void* const* d_in, const int* in_sizes, int n_in,
                              void* d_out, int out_size) {
    const float* x      = (const float*)d_in[0];
    const void*  ei     = d_in[1];
    const float* W_rel  = (const float*)d_in[2];
    const float* b_rel  = (const float*)d_in[3];
    const float* W_root = (const float*)d_in[4];
    const float* W1     = (const float*)d_in[5];
    const float* a1s    = (const float*)d_in[6];
    const float* a1d    = (const float*)d_in[7];
    const float* b1     = (const float*)d_in[8];
    const float* W2     = (const float*)d_in[9];
    const float* a2s    = (const float*)d_in[10];
    const float* a2d    = (const float*)d_in[11];
    const float* b2     = (const float*)d_in[12];
    const float* Wr     = (const float*)d_in[13];
    const float* br     = (const float*)d_in[14];
    float* out          = (float*)d_out;

    float *p_nbr, *p_h, *p_z1, *p_h2, *p_z2;
    cudaGetSymbolAddress((void**)&p_nbr, g_nbr);
    cudaGetSymbolAddress((void**)&p_h,   g_h);
    cudaGetSymbolAddress((void**)&p_z1,  g_z1);
    cudaGetSymbolAddress((void**)&p_h2,  g_h2);
    cudaGetSymbolAddress((void**)&p_z2,  g_z2);

    detect_kernel<<<1, 256>>>((const int*)ei);
    init_kernel<<<2048, 256>>>();
    scatter_x_kernel<<<(E * 32) / 256, 256>>>(x, ei);

    // h = elu(nbr @ W_rel^T + b_rel + x @ W_root^T)
    {
        dim3 g((N + 63) / 64, 2);
        linear_kernel<<<g, 128>>>(p_nbr, W_rel, 128, x, W_root, 128, b_rel, p_h, N, 128, 1);
    }
    // z1 = h @ W1^T
    {
        dim3 g((N + 63) / 64, 1);
        linear_kernel<<<g, 128>>>(p_h, W1, 128, nullptr, nullptr, 0, nullptr, p_z1, N, 64, 0);
    }
    alpha1_kernel<<<(N * 8 + 255) / 256, 256>>>(a1s, a1d);
    edge_max1<<<E / 256, 256>>>(ei);
    node_self1<<<(N * 8 + 255) / 256, 256>>>(a1s);
    edge_exp1<<<E / 256, 256>>>(ei);
    edge_agg1<<<(E * 16) / 256, 256>>>(ei);
    h2_kernel<<<(N * 16) / 256, 256>>>(b1);

    // z2 = h2 @ W2^T
    {
        dim3 g((N + 63) / 64, 1);
        linear_kernel<<<g, 128>>>(p_h2, W2, 64, nullptr, nullptr, 0, nullptr, p_z2, N, 64, 0);
    }
    alpha2_kernel<<<(N * 32) / 256, 256>>>(a2s, a2d);
    edge_max2<<<E / 256, 256>>>(ei);
    node_self2<<<(N + 255) / 256, 256>>>();
    edge_exp2<<<E / 256, 256>>>(ei);
    edge_agg2<<<(E * 16) / 256, 256>>>(ei);
    node_final<<<N / 16, 256>>>(b2);
    final_kernel<<<1, 64>>>(Wr, br, out);
}

// round 2
// speedup vs baseline: 1.4891x; 1.4891x over previous
#include <cuda_runtime.h>
#include <math.h>

constexpr int N = 50000;
constexpr int E = 800000;
constexpr int SCAN_B = 1024;
constexpr int NBLK = (N + SCAN_B - 1) / SCAN_B;   // 49

// ---------------------------------------------------------------------------
// Device scratch
// ---------------------------------------------------------------------------
__device__ __align__(16) float g_nbr[N * 128];
__device__ __align__(16) float g_h  [N * 128];
__device__ __align__(16) float g_z1 [N * 64];
__device__ __align__(16) float g_as1[N * 8];
__device__ __align__(16) float g_ad1[N * 8];
__device__ __align__(16) float g_h2 [N * 64];
__device__ __align__(16) float g_z2 [N * 64];
__device__ float g_as2[N];
__device__ float g_ad2[N];
__device__ __align__(16) float g_h3 [N * 64];
__device__ float g_gsum[64];
__device__ int g_deg[N];
__device__ int g_off[N];
__device__ int g_cur[N];
__device__ int g_csr[E];
__device__ int g_bsum[NBLK];
__device__ int g_is64;

// ---------------------------------------------------------------------------
// Helpers
// ---------------------------------------------------------------------------
__device__ __forceinline__ float lrelu(float x) { return x > 0.f ? x : 0.2f * x; }
__device__ __forceinline__ float elu1(float x)  { return x > 0.f ? x : expf(x) - 1.f; }

__device__ __forceinline__ int edge_id(const void* ei, long long idx) {
    return g_is64 ? (int)((const long long*)ei)[idx] : ((const int*)ei)[idx];
}
__device__ __forceinline__ int edge_src(const void* ei, int e) { return edge_id(ei, e); }
__device__ __forceinline__ int edge_dst(const void* ei, int e) { return edge_id(ei, (long long)E + e); }

__global__ void detect_kernel(const int* ei) {
    __shared__ int any;
    if (threadIdx.x == 0) any = 0;
    __syncthreads();
    for (int i = threadIdx.x; i < 1024; i += blockDim.x)
        if (ei[2 * i + 1] != 0) atomicOr(&any, 1);
    __syncthreads();
    if (threadIdx.x == 0) g_is64 = any ? 0 : 1;
}

__global__ void init_kernel() {
    int i = blockIdx.x * blockDim.x + threadIdx.x;
    int stride = gridDim.x * blockDim.x;
    for (int t = i; t < N; t += stride) { g_deg[t] = 0; g_cur[t] = 0; }
    if (i < 64) g_gsum[i] = 0.f;
}

// ---------------------------------------------------------------------------
// CSR build: histogram -> scan -> fill
// ---------------------------------------------------------------------------
__global__ void hist_kernel(const void* __restrict__ ei) {
    int e = blockIdx.x * blockDim.x + threadIdx.x;
    if (e >= E) return;
    atomicAdd(&g_deg[edge_dst(ei, e)], 1);
}

__global__ void scan1_kernel() {
    __shared__ int sm[SCAN_B];
    int t = threadIdx.x, b = blockIdx.x, i = b * SCAN_B + t;
    int v = (i < N) ? g_deg[i] : 0;
    sm[t] = v;
    __syncthreads();
    for (int o = 1; o < SCAN_B; o <<= 1) {
        int u = (t >= o) ? sm[t - o] : 0;
        __syncthreads();
        sm[t] += u;
        __syncthreads();
    }
    if (i < N) g_off[i] = sm[t] - v;   // exclusive
    if (t == SCAN_B - 1) g_bsum[b] = sm[t];
}

__global__ void scan2_kernel() {
    if (threadIdx.x == 0) {
        int acc = 0;
        for (int b = 0; b < NBLK; b++) { int v = g_bsum[b]; g_bsum[b] = acc; acc += v; }
    }
}

__global__ void scan3_kernel() {
    int i = blockIdx.x * SCAN_B + threadIdx.x;
    if (i < N) g_off[i] += g_bsum[blockIdx.x];
}

__global__ void fill_kernel(const void* __restrict__ ei) {
    int e = blockIdx.x * blockDim.x + threadIdx.x;
    if (e >= E) return;
    int s = edge_src(ei, e), d = edge_dst(ei, e);
    int pos = g_off[d] + atomicAdd(&g_cur[d], 1);
    g_csr[pos] = s;
}

// ---------------------------------------------------------------------------
// GraphConv neighbor gather: nbr[i] = sum_{s in N(i)} x[s]   (warp per node)
// ---------------------------------------------------------------------------
__global__ void gather_nbr_kernel(const float* __restrict__ x) {
    int gid = blockIdx.x * blockDim.x + threadIdx.x;
    int node = gid >> 5, lane = gid & 31;
    if (node >= N) return;
    int beg = g_off[node], deg = g_deg[node];
    float4 acc = make_float4(0.f, 0.f, 0.f, 0.f);
    for (int k = 0; k < deg; k++) {
        int s = g_csr[beg + k];
        float4 v = *(const float4*)(x + (size_t)s * 128 + lane * 4);
        acc.x += v.x; acc.y += v.y; acc.z += v.z; acc.w += v.w;
    }
    *(float4*)(g_nbr + (size_t)node * 128 + lane * 4) = acc;
}

// ---------------------------------------------------------------------------
// Tiled SGEMM: C = act( A1 @ Wa^T (+ A2 @ Wb^T) + bias )   (unchanged)
// ---------------------------------------------------------------------------
__global__ void linear_kernel(const float* __restrict__ A1, const float* __restrict__ Wa, int K1,
                              const float* __restrict__ A2, const float* __restrict__ Wb, int K2,
                              const float* __restrict__ bias, float* __restrict__ C,
                              int M, int NCOL, int act)
{
    __shared__ float As[64][65];
    __shared__ float Bs[64][65];
    const int tid  = threadIdx.x;
    const int row0 = blockIdx.x * 64;
    const int c0   = blockIdx.y * 64;
    const int rowg = tid >> 4;
    const int colg = tid & 15;

    float acc[8][4];
#pragma unroll
    for (int r = 0; r < 8; r++)
#pragma unroll
        for (int j = 0; j < 4; j++) acc[r][j] = 0.f;

    const int nk1 = K1 >> 6;
    const int nk2 = A2 ? (K2 >> 6) : 0;
    for (int t = 0; t < nk1 + nk2; t++) {
        const float* A; const float* W; int K; int kb;
        if (t < nk1) { A = A1; W = Wa; K = K1; kb = t << 6; }
        else         { A = A2; W = Wb; K = K2; kb = (t - nk1) << 6; }
#pragma unroll
        for (int it = 0; it < 8; it++) {
            int idx = tid + it * 128;
            int m   = idx >> 4;
            int k4  = (idx & 15) << 2;
            float4 av = make_float4(0.f, 0.f, 0.f, 0.f);
            if (row0 + m < M) av = *(const float4*)(A + (size_t)(row0 + m) * K + kb + k4);
            As[m][k4] = av.x; As[m][k4 + 1] = av.y; As[m][k4 + 2] = av.z; As[m][k4 + 3] = av.w;
            float4 bv = *(const float4*)(W + (size_t)(c0 + m) * K + kb + k4);
            Bs[m][k4] = bv.x; Bs[m][k4 + 1] = bv.y; Bs[m][k4 + 2] = bv.z; Bs[m][k4 + 3] = bv.w;
        }
        __syncthreads();
#pragma unroll 16
        for (int k = 0; k < 64; k++) {
            float a[8], b[4];
#pragma unroll
            for (int r = 0; r < 8; r++) a[r] = As[rowg * 8 + r][k];
#pragma unroll
            for (int j = 0; j < 4; j++) b[j] = Bs[colg * 4 + j][k];
#pragma unroll
            for (int r = 0; r < 8; r++)
#pragma unroll
                for (int j = 0; j < 4; j++)
                    acc[r][j] = fmaf(a[r], b[j], acc[r][j]);
        }
        __syncthreads();
    }
#pragma unroll
    for (int r = 0; r < 8; r++) {
        int gr = row0 + rowg * 8 + r;
        if (gr >= M) continue;
#pragma unroll
        for (int j = 0; j < 4; j++) {
            int gc = c0 + colg * 4 + j;
            float v = acc[r][j];
            if (bias) v += bias[gc];
            if (act == 1) v = elu1(v);
            C[(size_t)gr * NCOL + gc] = v;
        }
    }
}

// ---------------------------------------------------------------------------
// GAT1 alpha per node (8 heads x 8 ch)
// ---------------------------------------------------------------------------
__global__ void alpha1_kernel(const float* __restrict__ a1s, const float* __restrict__ a1d) {
    int gid = blockIdx.x * blockDim.x + threadIdx.x;
    if (gid >= N * 8) return;
    int i = gid >> 3, h = gid & 7;
    const float4* z = (const float4*)(g_z1 + (size_t)i * 64 + h * 8);
    float4 z0 = z[0], z1 = z[1];
    const float4* s4 = (const float4*)(a1s + h * 8);
    const float4* d4 = (const float4*)(a1d + h * 8);
    float4 s0 = s4[0], s1 = s4[1], d0 = d4[0], d1 = d4[1];
    g_as1[gid] = z0.x*s0.x + z0.y*s0.y + z0.z*s0.z + z0.w*s0.w
               + z1.x*s1.x + z1.y*s1.y + z1.z*s1.z + z1.w*s1.w;
    g_ad1[gid] = z0.x*d0.x + z0.y*d0.y + z0.z*d0.z + z0.w*d0.w
               + z1.x*d1.x + z1.y*d1.y + z1.z*d1.z + z1.w*d1.w;
}

// ---------------------------------------------------------------------------
// GAT1 fused: softmax + weighted aggregation, warp per node
// ---------------------------------------------------------------------------
__global__ void gat1_fused(const float* __restrict__ b1) {
    int gid = blockIdx.x * blockDim.x + threadIdx.x;
    int node = gid >> 5, lane = gid & 31;
    if (node >= N) return;
    int beg = g_off[node], deg = g_deg[node];

    float ad[8], asn[8];
    {
        const float4* p = (const float4*)(g_ad1 + (size_t)node * 8);
        float4 a = p[0], b = p[1];
        ad[0]=a.x; ad[1]=a.y; ad[2]=a.z; ad[3]=a.w; ad[4]=b.x; ad[5]=b.y; ad[6]=b.z; ad[7]=b.w;
        const float4* q = (const float4*)(g_as1 + (size_t)node * 8);
        float4 c = q[0], d = q[1];
        asn[0]=c.x; asn[1]=c.y; asn[2]=c.z; asn[3]=c.w; asn[4]=d.x; asn[5]=d.y; asn[6]=d.z; asn[7]=d.w;
    }

    // pass 1: max (self-loop included)
    float m[8];
#pragma unroll
    for (int h = 0; h < 8; h++) m[h] = lrelu(asn[h] + ad[h]);
    for (int k = lane; k < deg; k += 32) {
        int s = g_csr[beg + k];
        const float4* p = (const float4*)(g_as1 + (size_t)s * 8);
        float4 a = p[0], b = p[1];
        float sv[8] = {a.x, a.y, a.z, a.w, b.x, b.y, b.z, b.w};
#pragma unroll
        for (int h = 0; h < 8; h++) m[h] = fmaxf(m[h], lrelu(sv[h] + ad[h]));
    }
#pragma unroll
    for (int o = 16; o; o >>= 1)
#pragma unroll
        for (int h = 0; h < 8; h++) m[h] = fmaxf(m[h], __shfl_xor_sync(0xffffffff, m[h], o));

    // pass 2: denom
    float den[8];
#pragma unroll
    for (int h = 0; h < 8; h++) den[h] = (lane == 0) ? expf(lrelu(asn[h] + ad[h]) - m[h]) : 0.f;
    for (int k = lane; k < deg; k += 32) {
        int s = g_csr[beg + k];
        const float4* p = (const float4*)(g_as1 + (size_t)s * 8);
        float4 a = p[0], b = p[1];
        float sv[8] = {a.x, a.y, a.z, a.w, b.x, b.y, b.z, b.w};
#pragma unroll
        for (int h = 0; h < 8; h++) den[h] += expf(lrelu(sv[h] + ad[h]) - m[h]);
    }
#pragma unroll
    for (int o = 16; o; o >>= 1)
#pragma unroll
        for (int h = 0; h < 8; h++) den[h] += __shfl_xor_sync(0xffffffff, den[h], o);
    float rden[8];
#pragma unroll
    for (int h = 0; h < 8; h++) rden[h] = 1.f / (den[h] + 1e-16f);

    // pass 3: weighted aggregation. lane handles channels 2*lane, 2*lane+1; head = lane>>2
    int hh = lane >> 2;
    int c  = lane * 2;
    float adh = ad[hh], mh = m[hh], rh = rden[hh];
    float wslf = expf(lrelu(asn[hh] + adh) - mh) * rh;
    float2 zs = *(const float2*)(g_z1 + (size_t)node * 64 + c);
    float a0 = wslf * zs.x, a1 = wslf * zs.y;
    for (int k = 0; k < deg; k++) {
        int s = g_csr[beg + k];
        float w = expf(lrelu(g_as1[(size_t)s * 8 + hh] + adh) - mh) * rh;
        float2 z = *(const float2*)(g_z1 + (size_t)s * 64 + c);
        a0 += w * z.x; a1 += w * z.y;
    }
    float2 bb = *(const float2*)(b1 + c);
    a0 = elu1(a0 + bb.x); a1 = elu1(a1 + bb.y);
    *(float2*)(g_h2 + (size_t)node * 64 + c) = make_float2(a0, a1);
}

// ---------------------------------------------------------------------------
// GAT2 alpha (1 head, 64 ch)
// ---------------------------------------------------------------------------
__global__ void alpha2_kernel(const float* __restrict__ a2s, const float* __restrict__ a2d) {
    int gt = blockIdx.x * blockDim.x + threadIdx.x;
    int w = gt >> 5, lane = gt & 31;
    if (w >= N) return;
    float2 z  = ((const float2*)(g_z2 + (size_t)w * 64))[lane];
    float2 cs = ((const float2*)a2s)[lane];
    float2 cd = ((const float2*)a2d)[lane];
    float vs = z.x * cs.x + z.y * cs.y;
    float vd = z.x * cd.x + z.y * cd.y;
#pragma unroll
    for (int o = 16; o; o >>= 1) {
        vs += __shfl_down_sync(0xffffffff, vs, o);
        vd += __shfl_down_sync(0xffffffff, vd, o);
    }
    if (lane == 0) { g_as2[w] = vs; g_ad2[w] = vd; }
}

// ---------------------------------------------------------------------------
// GAT2 fused, warp per node; writes h3 = agg + b2 (no activation)
// ---------------------------------------------------------------------------
__global__ void gat2_fused(const float* __restrict__ b2) {
    int gid = blockIdx.x * blockDim.x + threadIdx.x;
    int node = gid >> 5, lane = gid & 31;
    if (node >= N) return;
    int beg = g_off[node], deg = g_deg[node];
    float adn = g_ad2[node], asn = g_as2[node];

    float m = lrelu(asn + adn);
    for (int k = lane; k < deg; k += 32)
        m = fmaxf(m, lrelu(g_as2[g_csr[beg + k]] + adn));
#pragma unroll
    for (int o = 16; o; o >>= 1) m = fmaxf(m, __shfl_xor_sync(0xffffffff, m, o));

    float den = (lane == 0) ? expf(lrelu(asn + adn) - m) : 0.f;
    for (int k = lane; k < deg; k += 32)
        den += expf(lrelu(g_as2[g_csr[beg + k]] + adn) - m);
#pragma unroll
    for (int o = 16; o; o >>= 1) den += __shfl_xor_sync(0xffffffff, den, o);
    float rden = 1.f / (den + 1e-16f);

    int c = lane * 2;
    float wslf = expf(lrelu(asn + adn) - m) * rden;
    float2 zs = *(const float2*)(g_z2 + (size_t)node * 64 + c);
    float a0 = wslf * zs.x, a1 = wslf * zs.y;
    for (int k = 0; k < deg; k++) {
        int s = g_csr[beg + k];
        float w = expf(lrelu(g_as2[s] + adn) - m) * rden;
        float2 z = *(const float2*)(g_z2 + (size_t)s * 64 + c);
        a0 += w * z.x; a1 += w * z.y;
    }
    float2 bb = *(const float2*)(b2 + c);
    *(float2*)(g_h3 + (size_t)node * 64 + c) = make_float2(a0 + bb.x, a1 + bb.y);
}

// ---------------------------------------------------------------------------
// Global mean reduction over nodes
// ---------------------------------------------------------------------------
__global__ void reduce_final() {
    int t = threadIdx.x;                 // 256
    int c = t & 63;
    int r0 = blockIdx.x * 4 + (t >> 6);  // 4 row-streams per block
    float acc = 0.f;
    for (int i = r0; i < N; i += gridDim.x * 4)
        acc += g_h3[(size_t)i * 64 + c];
    atomicAdd(&g_gsum[c], acc);
}

__global__ void final_kernel(const float* __restrict__ Wr, const float* __restrict__ br,
                             float* __restrict__ out) {
    __shared__ float sm[64];
    int t = threadIdx.x;  // 64
    sm[t] = g_gsum[t] * (1.0f / (float)N) * Wr[t];
    __syncthreads();
    if (t == 0) {
        float s = 0.f;
        for (int i = 0; i < 64; i++) s += sm[i];
        out[0] = s + br[0];
    }
}

// ---------------------------------------------------------------------------
// Launch
// ---------------------------------------------------------------------------
extern "C" void kernel_launch(void* const* d_in, const int* in_sizes, int n_in,
                              void* d_out, int out_size) {
    const float* x      = (const float*)d_in[0];
    const void*  ei     = d_in[1];
    const float* W_rel  = (const float*)d_in[2];
    const float* b_rel  = (const float*)d_in[3];
    const float* W_root = (const float*)d_in[4];
    const float* W1     = (const float*)d_in[5];
    const float* a1s    = (const float*)d_in[6];
    const float* a1d    = (const float*)d_in[7];
    const float* b1     = (const float*)d_in[8];
    const float* W2     = (const float*)d_in[9];
    const float* a2s    = (const float*)d_in[10];
    const float* a2d    = (const float*)d_in[11];
    const float* b2     = (const float*)d_in[12];
    const float* Wr     = (const float*)d_in[13];
    const float* br     = (const float*)d_in[14];
    float* out          = (float*)d_out;

    float *p_nbr, *p_h, *p_z1, *p_h2, *p_z2;
    cudaGetSymbolAddress((void**)&p_nbr, g_nbr);
    cudaGetSymbolAddress((void**)&p_h,   g_h);
    cudaGetSymbolAddress((void**)&p_z1,  g_z1);
    cudaGetSymbolAddress((void**)&p_h2,  g_h2);
    cudaGetSymbolAddress((void**)&p_z2,  g_z2);

    detect_kernel<<<1, 256>>>((const int*)ei);
    init_kernel<<<256, 256>>>();

    // CSR build (by dst), reused by all three layers
    hist_kernel<<<(E + 255) / 256, 256>>>(ei);
    scan1_kernel<<<NBLK, SCAN_B>>>();
    scan2_kernel<<<1, 32>>>();
    scan3_kernel<<<NBLK, SCAN_B>>>();
    fill_kernel<<<(E + 255) / 256, 256>>>(ei);

    // GraphConv
    gather_nbr_kernel<<<(N * 32 + 255) / 256, 256>>>(x);
    {
        dim3 g((N + 63) / 64, 2);
        linear_kernel<<<g, 128>>>(p_nbr, W_rel, 128, x, W_root, 128, b_rel, p_h, N, 128, 1);
    }

    // GAT1
    {
        dim3 g((N + 63) / 64, 1);
        linear_kernel<<<g, 128>>>(p_h, W1, 128, nullptr, nullptr, 0, nullptr, p_z1, N, 64, 0);
    }
    alpha1_kernel<<<(N * 8 + 255) / 256, 256>>>(a1s, a1d);
    gat1_fused<<<(N * 32 + 255) / 256, 256>>>(b1);

    // GAT2
    {
        dim3 g((N + 63) / 64, 1);
        linear_kernel<<<g, 128>>>(p_h2, W2, 64, nullptr, nullptr, 0, nullptr, p_z2, N, 64, 0);
    }
    alpha2_kernel<<<(N * 32 + 255) / 256, 256>>>(a2s, a2d);
    gat2_fused<<<(N * 32 + 255) / 256, 256>>>(b2);

    // Global mean + regression head
    reduce_final<<<128, 256>>>();
    final_kernel<<<1, 64>>>(Wr, br, out);
}

// round 3
// speedup vs baseline: 1.7404x; 1.1687x over previous
#include <cuda_runtime.h>
#include <math.h>
#include <stdint.h>

constexpr int N = 50000;
constexpr int E = 800000;
constexpr int SCAN_B = 1024;
constexpr int NBLK = (N + SCAN_B - 1) / SCAN_B;   // 49

// ---------------------------------------------------------------------------
// Device scratch
// ---------------------------------------------------------------------------
__device__ __align__(16) float g_nbr[N * 128];
__device__ __align__(16) float g_h  [N * 128];
__device__ __align__(16) float g_z1 [N * 64];
__device__ __align__(16) float g_as1[N * 8];
__device__ __align__(16) float g_ad1[N * 8];
__device__ __align__(16) float g_h2 [N * 64];
__device__ __align__(16) float g_z2 [N * 64];
__device__ float g_as2[N];
__device__ float g_ad2[N];
__device__ __align__(16) float g_h3 [N * 64];
__device__ float g_gsum[64];
__device__ int g_deg[N];
__device__ int g_off[N];
__device__ int g_cur[N];
__device__ int g_csr[E];
__device__ int g_bsum[NBLK];
__device__ int g_is64;

// ---------------------------------------------------------------------------
// Helpers
// ---------------------------------------------------------------------------
__device__ __forceinline__ float lrelu(float x) { return x > 0.f ? x : 0.2f * x; }
__device__ __forceinline__ float elu1(float x)  { return x > 0.f ? x : expf(x) - 1.f; }

__device__ __forceinline__ uint32_t f2tf32(float x) {
    uint32_t r;
    asm("cvt.rna.tf32.f32 %0, %1;" : "=r"(r) : "f"(x));
    return r;
}

__device__ __forceinline__ void mma_tf32(float c[4], const uint4& a, const uint2& b) {
    asm volatile(
        "mma.sync.aligned.m16n8k8.row.col.f32.tf32.tf32.f32 "
        "{%0,%1,%2,%3}, {%4,%5,%6,%7}, {%8,%9}, {%0,%1,%2,%3};"
        : "+f"(c[0]), "+f"(c[1]), "+f"(c[2]), "+f"(c[3])
        : "r"(a.x), "r"(a.y), "r"(a.z), "r"(a.w), "r"(b.x), "r"(b.y));
}

__device__ __forceinline__ int edge_id(const void* ei, long long idx) {
    return g_is64 ? (int)((const long long*)ei)[idx] : ((const int*)ei)[idx];
}
__device__ __forceinline__ int edge_src(const void* ei, int e) { return edge_id(ei, e); }
__device__ __forceinline__ int edge_dst(const void* ei, int e) { return edge_id(ei, (long long)E + e); }

__global__ void detect_kernel(const int* ei) {
    __shared__ int any;
    if (threadIdx.x == 0) any = 0;
    __syncthreads();
    for (int i = threadIdx.x; i < 1024; i += blockDim.x)
        if (ei[2 * i + 1] != 0) atomicOr(&any, 1);
    __syncthreads();
    if (threadIdx.x == 0) g_is64 = any ? 0 : 1;
}

__global__ void init_kernel() {
    int i = blockIdx.x * blockDim.x + threadIdx.x;
    int stride = gridDim.x * blockDim.x;
    for (int t = i; t < N; t += stride) { g_deg[t] = 0; g_cur[t] = 0; }
    if (i < 64) g_gsum[i] = 0.f;
}

// ---------------------------------------------------------------------------
// CSR build
// ---------------------------------------------------------------------------
__global__ void hist_kernel(const void* __restrict__ ei) {
    int e = blockIdx.x * blockDim.x + threadIdx.x;
    if (e >= E) return;
    atomicAdd(&g_deg[edge_dst(ei, e)], 1);
}

__global__ void scan1_kernel() {
    __shared__ int sm[SCAN_B];
    int t = threadIdx.x, b = blockIdx.x, i = b * SCAN_B + t;
    int v = (i < N) ? g_deg[i] : 0;
    sm[t] = v;
    __syncthreads();
    for (int o = 1; o < SCAN_B; o <<= 1) {
        int u = (t >= o) ? sm[t - o] : 0;
        __syncthreads();
        sm[t] += u;
        __syncthreads();
    }
    if (i < N) g_off[i] = sm[t] - v;
    if (t == SCAN_B - 1) g_bsum[b] = sm[t];
}

__global__ void scan2_kernel() {
    if (threadIdx.x == 0) {
        int acc = 0;
        for (int b = 0; b < NBLK; b++) { int v = g_bsum[b]; g_bsum[b] = acc; acc += v; }
    }
}

__global__ void scan3_kernel() {
    int i = blockIdx.x * SCAN_B + threadIdx.x;
    if (i < N) g_off[i] += g_bsum[blockIdx.x];
}

__global__ void fill_kernel(const void* __restrict__ ei) {
    int e = blockIdx.x * blockDim.x + threadIdx.x;
    if (e >= E) return;
    int s = edge_src(ei, e), d = edge_dst(ei, e);
    int pos = g_off[d] + atomicAdd(&g_cur[d], 1);
    g_csr[pos] = s;
}

// ---------------------------------------------------------------------------
// GraphConv neighbor gather (warp per node)
// ---------------------------------------------------------------------------
__global__ void gather_nbr_kernel(const float* __restrict__ x) {
    int gid = blockIdx.x * blockDim.x + threadIdx.x;
    int node = gid >> 5, lane = gid & 31;
    if (node >= N) return;
    int beg = g_off[node], deg = g_deg[node];
    float4 acc = make_float4(0.f, 0.f, 0.f, 0.f);
    for (int k = 0; k < deg; k++) {
        int s = g_csr[beg + k];
        float4 v = *(const float4*)(x + (size_t)s * 128 + lane * 4);
        acc.x += v.x; acc.y += v.y; acc.z += v.z; acc.w += v.w;
    }
    *(float4*)(g_nbr + (size_t)node * 128 + lane * 4) = acc;
}

// ---------------------------------------------------------------------------
// tf32 tensor-core GEMM: C = act( A1 @ Wa^T (+ A2 @ Wb^T) + bias )
// A row-major [M,K], W row-major [NCOL,K]. BM=128 BN=64 BK=32, 256 threads.
// Fragments staged to smem in mma fragment order.
// ---------------------------------------------------------------------------
__global__ __launch_bounds__(256) void tf32_linear(
    const float* __restrict__ A1, const float* __restrict__ Wa, int K1,
    const float* __restrict__ A2, const float* __restrict__ Wb, int K2,
    const float* __restrict__ bias, float* __restrict__ C,
    int M, int NCOL, int act)
{
    __shared__ __align__(16) uint32_t As[4][8][128];  // [k8][m16][lane*4+reg] 16KB
    __shared__ __align__(16) uint32_t Bs[4][8][64];   // [k8][n8][lane*2+reg]   8KB
    const int tid  = threadIdx.x;
    const int lane = tid & 31, warp = tid >> 5;
    const int wm = warp & 3, wn = warp >> 2;          // 4 m-warps x 2 n-warps
    const int row0 = blockIdx.x * 128, c0 = blockIdx.y * 64;

    float acc[2][4][4];
#pragma unroll
    for (int mt = 0; mt < 2; mt++)
#pragma unroll
        for (int nt = 0; nt < 4; nt++)
#pragma unroll
            for (int j = 0; j < 4; j++) acc[mt][nt][j] = 0.f;

    const int nk1 = K1 >> 5;
    const int nk2 = A2 ? (K2 >> 5) : 0;
    for (int t = 0; t < nk1 + nk2; t++) {
        const float* A; const float* W; int K, kb;
        if (t < nk1) { A = A1; W = Wa; K = K1; kb = t << 5; }
        else         { A = A2; W = Wb; K = K2; kb = (t - nk1) << 5; }
        __syncthreads();   // protect smem from previous iteration's readers
        // stage A tile 128x32 -> fragment order
#pragma unroll
        for (int i = 0; i < 4; i++) {
            int idx = tid + i * 256;
            int m = idx >> 3, k4 = (idx & 7) << 2;
            float4 v = make_float4(0.f, 0.f, 0.f, 0.f);
            if (row0 + m < M) v = *(const float4*)(A + (size_t)(row0 + m) * K + kb + k4);
            float vv[4] = {v.x, v.y, v.z, v.w};
            int m16 = m >> 4, mm = m & 15, r = mm & 7, rr = mm >> 3;
#pragma unroll
            for (int j = 0; j < 4; j++) {
                int k = k4 + j;
                int reg = ((k & 7) >> 2) * 2 + rr;
                As[k >> 3][m16][(r * 4 + (k & 3)) * 4 + reg] = f2tf32(vv[j]);
            }
        }
        // stage W tile 64x32 -> fragment order
#pragma unroll
        for (int i = 0; i < 2; i++) {
            int idx = tid + i * 256;
            int n = idx >> 3, k4 = (idx & 7) << 2;
            float4 v = *(const float4*)(W + (size_t)(c0 + n) * K + kb + k4);
            float vv[4] = {v.x, v.y, v.z, v.w};
            int n8 = n >> 3, nn = n & 7;
#pragma unroll
            for (int j = 0; j < 4; j++) {
                int k = k4 + j;
                Bs[k >> 3][n8][(nn * 4 + (k & 3)) * 2 + ((k & 7) >> 2)] = f2tf32(vv[j]);
            }
        }
        __syncthreads();
#pragma unroll
        for (int k8 = 0; k8 < 4; k8++) {
            uint4 a[2];
            uint2 b[4];
            a[0] = *(const uint4*)&As[k8][wm * 2 + 0][lane * 4];
            a[1] = *(const uint4*)&As[k8][wm * 2 + 1][lane * 4];
#pragma unroll
            for (int nt = 0; nt < 4; nt++)
                b[nt] = *(const uint2*)&Bs[k8][wn * 4 + nt][lane * 2];
#pragma unroll
            for (int mt = 0; mt < 2; mt++)
#pragma unroll
                for (int nt = 0; nt < 4; nt++)
                    mma_tf32(acc[mt][nt], a[mt], b[nt]);
        }
    }

    // epilogue
    const int r = lane >> 2, cc = (lane & 3) * 2;
#pragma unroll
    for (int mt = 0; mt < 2; mt++) {
#pragma unroll
        for (int nt = 0; nt < 4; nt++) {
            int col = c0 + (wn * 4 + nt) * 8 + cc;
            float bx = 0.f, by = 0.f;
            if (bias) { bx = bias[col]; by = bias[col + 1]; }
            int row = row0 + (wm * 2 + mt) * 16 + r;
            if (row < M) {
                float v0 = acc[mt][nt][0] + bx, v1 = acc[mt][nt][1] + by;
                if (act == 1) { v0 = elu1(v0); v1 = elu1(v1); }
                *(float2*)(C + (size_t)row * NCOL + col) = make_float2(v0, v1);
            }
            int row2 = row + 8;
            if (row2 < M) {
                float v2 = acc[mt][nt][2] + bx, v3 = acc[mt][nt][3] + by;
                if (act == 1) { v2 = elu1(v2); v3 = elu1(v3); }
                *(float2*)(C + (size_t)row2 * NCOL + col) = make_float2(v2, v3);
            }
        }
    }
}

// ---------------------------------------------------------------------------
// GAT1 alpha per node
// ---------------------------------------------------------------------------
__global__ void alpha1_kernel(const float* __restrict__ a1s, const float* __restrict__ a1d) {
    int gid = blockIdx.x * blockDim.x + threadIdx.x;
    if (gid >= N * 8) return;
    int i = gid >> 3, h = gid & 7;
    const float4* z = (const float4*)(g_z1 + (size_t)i * 64 + h * 8);
    float4 z0 = z[0], z1 = z[1];
    const float4* s4 = (const float4*)(a1s + h * 8);
    const float4* d4 = (const float4*)(a1d + h * 8);
    float4 s0 = s4[0], s1 = s4[1], d0 = d4[0], d1 = d4[1];
    g_as1[gid] = z0.x*s0.x + z0.y*s0.y + z0.z*s0.z + z0.w*s0.w
               + z1.x*s1.x + z1.y*s1.y + z1.z*s1.z + z1.w*s1.w;
    g_ad1[gid] = z0.x*d0.x + z0.y*d0.y + z0.z*d0.z + z0.w*d0.w
               + z1.x*d1.x + z1.y*d1.y + z1.z*d1.z + z1.w*d1.w;
}

// ---------------------------------------------------------------------------
// GAT1 fused softmax + aggregation (warp per node)
// ---------------------------------------------------------------------------
__global__ void gat1_fused(const float* __restrict__ b1) {
    int gid = blockIdx.x * blockDim.x + threadIdx.x;
    int node = gid >> 5, lane = gid & 31;
    if (node >= N) return;
    int beg = g_off[node], deg = g_deg[node];

    float ad[8], asn[8];
    {
        const float4* p = (const float4*)(g_ad1 + (size_t)node * 8);
        float4 a = p[0], b = p[1];
        ad[0]=a.x; ad[1]=a.y; ad[2]=a.z; ad[3]=a.w; ad[4]=b.x; ad[5]=b.y; ad[6]=b.z; ad[7]=b.w;
        const float4* q = (const float4*)(g_as1 + (size_t)node * 8);
        float4 c = q[0], d = q[1];
        asn[0]=c.x; asn[1]=c.y; asn[2]=c.z; asn[3]=c.w; asn[4]=d.x; asn[5]=d.y; asn[6]=d.z; asn[7]=d.w;
    }

    float m[8];
#pragma unroll
    for (int h = 0; h < 8; h++) m[h] = lrelu(asn[h] + ad[h]);
    for (int k = lane; k < deg; k += 32) {
        int s = g_csr[beg + k];
        const float4* p = (const float4*)(g_as1 + (size_t)s * 8);
        float4 a = p[0], b = p[1];
        float sv[8] = {a.x, a.y, a.z, a.w, b.x, b.y, b.z, b.w};
#pragma unroll
        for (int h = 0; h < 8; h++) m[h] = fmaxf(m[h], lrelu(sv[h] + ad[h]));
    }
#pragma unroll
    for (int o = 16; o; o >>= 1)
#pragma unroll
        for (int h = 0; h < 8; h++) m[h] = fmaxf(m[h], __shfl_xor_sync(0xffffffff, m[h], o));

    float den[8];
#pragma unroll
    for (int h = 0; h < 8; h++) den[h] = (lane == 0) ? expf(lrelu(asn[h] + ad[h]) - m[h]) : 0.f;
    for (int k = lane; k < deg; k += 32) {
        int s = g_csr[beg + k];
        const float4* p = (const float4*)(g_as1 + (size_t)s * 8);
        float4 a = p[0], b = p[1];
        float sv[8] = {a.x, a.y, a.z, a.w, b.x, b.y, b.z, b.w};
#pragma unroll
        for (int h = 0; h < 8; h++) den[h] += expf(lrelu(sv[h] + ad[h]) - m[h]);
    }
#pragma unroll
    for (int o = 16; o; o >>= 1)
#pragma unroll
        for (int h = 0; h < 8; h++) den[h] += __shfl_xor_sync(0xffffffff, den[h], o);
    float rden[8];
#pragma unroll
    for (int h = 0; h < 8; h++) rden[h] = 1.f / (den[h] + 1e-16f);

    int hh = lane >> 2;
    int c  = lane * 2;
    float adh = ad[hh], mh = m[hh], rh = rden[hh];
    float wslf = expf(lrelu(asn[hh] + adh) - mh) * rh;
    float2 zs = *(const float2*)(g_z1 + (size_t)node * 64 + c);
    float a0 = wslf * zs.x, a1 = wslf * zs.y;
    for (int k = 0; k < deg; k++) {
        int s = g_csr[beg + k];
        float w = expf(lrelu(g_as1[(size_t)s * 8 + hh] + adh) - mh) * rh;
        float2 z = *(const float2*)(g_z1 + (size_t)s * 64 + c);
        a0 += w * z.x; a1 += w * z.y;
    }
    float2 bb = *(const float2*)(b1 + c);
    a0 = elu1(a0 + bb.x); a1 = elu1(a1 + bb.y);
    *(float2*)(g_h2 + (size_t)node * 64 + c) = make_float2(a0, a1);
}

// ---------------------------------------------------------------------------
// GAT2 alpha (1 head, 64 ch)
// ---------------------------------------------------------------------------
__global__ void alpha2_kernel(const float* __restrict__ a2s, const float* __restrict__ a2d) {
    int gt = blockIdx.x * blockDim.x + threadIdx.x;
    int w = gt >> 5, lane = gt & 31;
    if (w >= N) return;
    float2 z  = ((const float2*)(g_z2 + (size_t)w * 64))[lane];
    float2 cs = ((const float2*)a2s)[lane];
    float2 cd = ((const float2*)a2d)[lane];
    float vs = z.x * cs.x + z.y * cs.y;
    float vd = z.x * cd.x + z.y * cd.y;
#pragma unroll
    for (int o = 16; o; o >>= 1) {
        vs += __shfl_down_sync(0xffffffff, vs, o);
        vd += __shfl_down_sync(0xffffffff, vd, o);
    }
    if (lane == 0) { g_as2[w] = vs; g_ad2[w] = vd; }
}

// ---------------------------------------------------------------------------
// GAT2 fused (warp per node)
// ---------------------------------------------------------------------------
__global__ void gat2_fused(const float* __restrict__ b2) {
    int gid = blockIdx.x * blockDim.x + threadIdx.x;
    int node = gid >> 5, lane = gid & 31;
    if (node >= N) return;
    int beg = g_off[node], deg = g_deg[node];
    float adn = g_ad2[node], asn = g_as2[node];

    float m = lrelu(asn + adn);
    for (int k = lane; k < deg; k += 32)
        m = fmaxf(m, lrelu(g_as2[g_csr[beg + k]] + adn));
#pragma unroll
    for (int o = 16; o; o >>= 1) m = fmaxf(m, __shfl_xor_sync(0xffffffff, m, o));

    float den = (lane == 0) ? expf(lrelu(asn + adn) - m) : 0.f;
    for (int k = lane; k < deg; k += 32)
        den += expf(lrelu(g_as2[g_csr[beg + k]] + adn) - m);
#pragma unroll
    for (int o = 16; o; o >>= 1) den += __shfl_xor_sync(0xffffffff, den, o);
    float rden = 1.f / (den + 1e-16f);

    int c = lane * 2;
    float wslf = expf(lrelu(asn + adn) - m) * rden;
    float2 zs = *(const float2*)(g_z2 + (size_t)node * 64 + c);
    float a0 = wslf * zs.x, a1 = wslf * zs.y;
    for (int k = 0; k < deg; k++) {
        int s = g_csr[beg + k];
        float w = expf(lrelu(g_as2[s] + adn) - m) * rden;
        float2 z = *(const float2*)(g_z2 + (size_t)s * 64 + c);
        a0 += w * z.x; a1 += w * z.y;
    }
    float2 bb = *(const float2*)(b2 + c);
    *(float2*)(g_h3 + (size_t)node * 64 + c) = make_float2(a0 + bb.x, a1 + bb.y);
}

// ---------------------------------------------------------------------------
// Global mean + head
// ---------------------------------------------------------------------------
__global__ void reduce_final() {
    int t = threadIdx.x;
    int c = t & 63;
    int r0 = blockIdx.x * 4 + (t >> 6);
    float acc = 0.f;
    for (int i = r0; i < N; i += gridDim.x * 4)
        acc += g_h3[(size_t)i * 64 + c];
    atomicAdd(&g_gsum[c], acc);
}

__global__ void final_kernel(const float* __restrict__ Wr, const float* __restrict__ br,
                             float* __restrict__ out) {
    __shared__ float sm[64];
    int t = threadIdx.x;
    sm[t] = g_gsum[t] * (1.0f / (float)N) * Wr[t];
    __syncthreads();
    if (t == 0) {
        float s = 0.f;
        for (int i = 0; i < 64; i++) s += sm[i];
        out[0] = s + br[0];
    }
}

// ---------------------------------------------------------------------------
// Launch
// ---------------------------------------------------------------------------
extern "C" void kernel_launch(void* const* d_in, const int* in_sizes, int n_in,
                              void* d_out, int out_size) {
    const float* x      = (const float*)d_in[0];
    const void*  ei     = d_in[1];
    const float* W_rel  = (const float*)d_in[2];
    const float* b_rel  = (const float*)d_in[3];
    const float* W_root = (const float*)d_in[4];
    const float* W1     = (const float*)d_in[5];
    const float* a1s    = (const float*)d_in[6];
    const float* a1d    = (const float*)d_in[7];
    const float* b1     = (const float*)d_in[8];
    const float* W2     = (const float*)d_in[9];
    const float* a2s    = (const float*)d_in[10];
    const float* a2d    = (const float*)d_in[11];
    const float* b2     = (const float*)d_in[12];
    const float* Wr     = (const float*)d_in[13];
    const float* br     = (const float*)d_in[14];
    float* out          = (float*)d_out;

    float *p_nbr, *p_h, *p_z1, *p_h2, *p_z2;
    cudaGetSymbolAddress((void**)&p_nbr, g_nbr);
    cudaGetSymbolAddress((void**)&p_h,   g_h);
    cudaGetSymbolAddress((void**)&p_z1,  g_z1);
    cudaGetSymbolAddress((void**)&p_h2,  g_h2);
    cudaGetSymbolAddress((void**)&p_z2,  g_z2);

    detect_kernel<<<1, 256>>>((const int*)ei);
    init_kernel<<<256, 256>>>();

    hist_kernel<<<(E + 255) / 256, 256>>>(ei);
    scan1_kernel<<<NBLK, SCAN_B>>>();
    scan2_kernel<<<1, 32>>>();
    scan3_kernel<<<NBLK, SCAN_B>>>();
    fill_kernel<<<(E + 255) / 256, 256>>>(ei);

    gather_nbr_kernel<<<(N * 32 + 255) / 256, 256>>>(x);
    {
        dim3 g((N + 127) / 128, 2);
        tf32_linear<<<g, 256>>>(p_nbr, W_rel, 128, x, W_root, 128, b_rel, p_h, N, 128, 1);
    }
    {
        dim3 g((N + 127) / 128, 1);
        tf32_linear<<<g, 256>>>(p_h, W1, 128, nullptr, nullptr, 0, nullptr, p_z1, N, 64, 0);
    }
    alpha1_kernel<<<(N * 8 + 255) / 256, 256>>>(a1s, a1d);
    gat1_fused<<<(N * 32 + 255) / 256, 256>>>(b1);

    {
        dim3 g((N + 127) / 128, 1);
        tf32_linear<<<g, 256>>>(p_h2, W2, 64, nullptr, nullptr, 0, nullptr, p_z2, N, 64, 0);
    }
    alpha2_kernel<<<(N * 32 + 255) / 256, 256>>>(a2s, a2d);
    gat2_fused<<<(N * 32 + 255) / 256, 256>>>(b2);

    reduce_final<<<128, 256>>>();
    final_kernel<<<1, 64>>>(Wr, br, out);
}

// round 4
// speedup vs baseline: 2.0800x; 1.1951x over previous
#include <cuda_runtime.h>
#include <math.h>
#include <stdint.h>

constexpr int N = 50000;
constexpr int E = 800000;
constexpr int SCAN_B = 1024;
constexpr int NBLK = (N + SCAN_B - 1) / SCAN_B;   // 49

// ---------------------------------------------------------------------------
// Device scratch
// ---------------------------------------------------------------------------
__device__ __align__(16) float g_nbr[N * 128];
__device__ __align__(16) float g_h  [N * 128];
__device__ __align__(16) float g_z1 [N * 64];
__device__ __align__(16) float g_as1[N * 8];
__device__ __align__(16) float g_ad1[N * 8];
__device__ __align__(16) float g_h2 [N * 64];
__device__ __align__(16) float g_z2 [N * 64];
__device__ float g_as2[N];
__device__ float g_ad2[N];
__device__ __align__(16) float g_h3 [N * 64];
__device__ float g_gsum[64];
__device__ int g_deg[N];
__device__ int g_off[N];
__device__ int g_cur[N];
__device__ int g_csr[E];
__device__ int g_bsum[NBLK];
__device__ int g_is64;

// ---------------------------------------------------------------------------
// Helpers
// ---------------------------------------------------------------------------
__device__ __forceinline__ float lrelu(float x) { return x > 0.f ? x : 0.2f * x; }
__device__ __forceinline__ float elu1(float x)  { return x > 0.f ? x : __expf(x) - 1.f; }

__device__ __forceinline__ uint32_t f2tf32(float x) {
    uint32_t r;
    asm("cvt.rna.tf32.f32 %0, %1;" : "=r"(r) : "f"(x));
    return r;
}

__device__ __forceinline__ void mma_tf32(float c[4], const uint4& a, const uint2& b) {
    asm volatile(
        "mma.sync.aligned.m16n8k8.row.col.f32.tf32.tf32.f32 "
        "{%0,%1,%2,%3}, {%4,%5,%6,%7}, {%8,%9}, {%0,%1,%2,%3};"
        : "+f"(c[0]), "+f"(c[1]), "+f"(c[2]), "+f"(c[3])
        : "r"(a.x), "r"(a.y), "r"(a.z), "r"(a.w), "r"(b.x), "r"(b.y));
}

__device__ __forceinline__ int edge_id(const void* ei, long long idx) {
    return g_is64 ? (int)((const long long*)ei)[idx] : ((const int*)ei)[idx];
}
__device__ __forceinline__ int edge_src(const void* ei, int e) { return edge_id(ei, e); }
__device__ __forceinline__ int edge_dst(const void* ei, int e) { return edge_id(ei, (long long)E + e); }

// ---------------------------------------------------------------------------
// init (zero counters) + dtype detect (block 0)
// ---------------------------------------------------------------------------
__global__ void init_kernel(const int* ei) {
    int i = blockIdx.x * blockDim.x + threadIdx.x;
    int stride = gridDim.x * blockDim.x;
    for (int t = i; t < N; t += stride) { g_deg[t] = 0; g_cur[t] = 0; }
    if (i < 64) g_gsum[i] = 0.f;
    if (blockIdx.x == 0) {
        __shared__ int any;
        if (threadIdx.x == 0) any = 0;
        __syncthreads();
        for (int t = threadIdx.x; t < 1024; t += blockDim.x)
            if (ei[2 * t + 1] != 0) atomicOr(&any, 1);
        __syncthreads();
        if (threadIdx.x == 0) g_is64 = any ? 0 : 1;
    }
}

// ---------------------------------------------------------------------------
// CSR build
// ---------------------------------------------------------------------------
__global__ void hist_kernel(const void* __restrict__ ei) {
    int e = blockIdx.x * blockDim.x + threadIdx.x;
    if (e >= E) return;
    atomicAdd(&g_deg[edge_dst(ei, e)], 1);
}

__global__ void scan1_kernel() {
    __shared__ int sm[SCAN_B];
    int t = threadIdx.x, b = blockIdx.x, i = b * SCAN_B + t;
    int v = (i < N) ? g_deg[i] : 0;
    sm[t] = v;
    __syncthreads();
    for (int o = 1; o < SCAN_B; o <<= 1) {
        int u = (t >= o) ? sm[t - o] : 0;
        __syncthreads();
        sm[t] += u;
        __syncthreads();
    }
    if (i < N) g_off[i] = sm[t] - v;
    if (t == SCAN_B - 1) g_bsum[b] = sm[t];
}

__global__ void scan2_kernel() {
    __shared__ int sm[64];
    int t = threadIdx.x;   // 64
    int v = (t < NBLK) ? g_bsum[t] : 0;
    sm[t] = v;
    __syncthreads();
    for (int o = 1; o < 64; o <<= 1) {
        int u = (t >= o) ? sm[t - o] : 0;
        __syncthreads();
        sm[t] += u;
        __syncthreads();
    }
    if (t < NBLK) g_bsum[t] = sm[t] - v;   // exclusive
}

__global__ void scan3_kernel() {
    int i = blockIdx.x * SCAN_B + threadIdx.x;
    if (i < N) g_off[i] += g_bsum[blockIdx.x];
}

__global__ void fill_kernel(const void* __restrict__ ei) {
    int e = blockIdx.x * blockDim.x + threadIdx.x;
    if (e >= E) return;
    int s = edge_src(ei, e), d = edge_dst(ei, e);
    int pos = g_off[d] + atomicAdd(&g_cur[d], 1);
    g_csr[pos] = s;
}

// ---------------------------------------------------------------------------
// GraphConv neighbor gather (warp per node, 2x unrolled)
// ---------------------------------------------------------------------------
__global__ void gather_nbr_kernel(const float* __restrict__ x) {
    int gid = blockIdx.x * blockDim.x + threadIdx.x;
    int node = gid >> 5, lane = gid & 31;
    if (node >= N) return;
    int beg = g_off[node], deg = g_deg[node];
    float4 acc = make_float4(0.f, 0.f, 0.f, 0.f);
    int k = 0;
    for (; k + 2 <= deg; k += 2) {
        int s0 = g_csr[beg + k], s1 = g_csr[beg + k + 1];
        float4 v0 = *(const float4*)(x + (size_t)s0 * 128 + lane * 4);
        float4 v1 = *(const float4*)(x + (size_t)s1 * 128 + lane * 4);
        acc.x += v0.x + v1.x; acc.y += v0.y + v1.y;
        acc.z += v0.z + v1.z; acc.w += v0.w + v1.w;
    }
    if (k < deg) {
        int s = g_csr[beg + k];
        float4 v = *(const float4*)(x + (size_t)s * 128 + lane * 4);
        acc.x += v.x; acc.y += v.y; acc.z += v.z; acc.w += v.w;
    }
    *(float4*)(g_nbr + (size_t)node * 128 + lane * 4) = acc;
}

// ---------------------------------------------------------------------------
// tf32 GEMM: C = act( A1 @ Wa^T (+ A2 @ Wb^T) + bias ); BM=128, BN template
// ---------------------------------------------------------------------------
template<int BN>
__global__ __launch_bounds__(256) void tf32_linear(
    const float* __restrict__ A1, const float* __restrict__ Wa, int K1,
    const float* __restrict__ A2, const float* __restrict__ Wb, int K2,
    const float* __restrict__ bias, float* __restrict__ C,
    int M, int NCOL, int act)
{
    constexpr int NT = BN / 16;                        // n-tiles per warp
    __shared__ __align__(16) uint32_t As[4][8][128];   // [k8][m16][lane*4+reg]
    __shared__ __align__(16) uint32_t Bs[4][BN / 8][64];
    const int tid  = threadIdx.x;
    const int lane = tid & 31, warp = tid >> 5;
    const int wm = warp & 3, wn = warp >> 2;
    const int row0 = blockIdx.x * 128, c0 = blockIdx.y * BN;

    float acc[2][NT][4];
#pragma unroll
    for (int mt = 0; mt < 2; mt++)
#pragma unroll
        for (int nt = 0; nt < NT; nt++)
#pragma unroll
            for (int j = 0; j < 4; j++) acc[mt][nt][j] = 0.f;

    const int nk1 = K1 >> 5;
    const int nk2 = A2 ? (K2 >> 5) : 0;
    for (int t = 0; t < nk1 + nk2; t++) {
        const float* A; const float* W; int K, kb;
        if (t < nk1) { A = A1; W = Wa; K = K1; kb = t << 5; }
        else         { A = A2; W = Wb; K = K2; kb = (t - nk1) << 5; }
        __syncthreads();
#pragma unroll
        for (int i = 0; i < 4; i++) {
            int idx = tid + i * 256;
            int m = idx >> 3, k4 = (idx & 7) << 2;
            float4 v = make_float4(0.f, 0.f, 0.f, 0.f);
            if (row0 + m < M) v = *(const float4*)(A + (size_t)(row0 + m) * K + kb + k4);
            float vv[4] = {v.x, v.y, v.z, v.w};
            int m16 = m >> 4, mm = m & 15, r = mm & 7, rr = mm >> 3;
#pragma unroll
            for (int j = 0; j < 4; j++) {
                int k = k4 + j;
                int reg = ((k & 7) >> 2) * 2 + rr;
                As[k >> 3][m16][(r * 4 + (k & 3)) * 4 + reg] = f2tf32(vv[j]);
            }
        }
#pragma unroll
        for (int i = 0; i < BN / 32; i++) {
            int idx = tid + i * 256;
            int n = idx >> 3, k4 = (idx & 7) << 2;
            float4 v = *(const float4*)(W + (size_t)(c0 + n) * K + kb + k4);
            float vv[4] = {v.x, v.y, v.z, v.w};
            int n8 = n >> 3, nn = n & 7;
#pragma unroll
            for (int j = 0; j < 4; j++) {
                int k = k4 + j;
                Bs[k >> 3][n8][(nn * 4 + (k & 3)) * 2 + ((k & 7) >> 2)] = f2tf32(vv[j]);
            }
        }
        __syncthreads();
#pragma unroll
        for (int k8 = 0; k8 < 4; k8++) {
            uint4 a[2];
            uint2 b[NT];
            a[0] = *(const uint4*)&As[k8][wm * 2 + 0][lane * 4];
            a[1] = *(const uint4*)&As[k8][wm * 2 + 1][lane * 4];
#pragma unroll
            for (int nt = 0; nt < NT; nt++)
                b[nt] = *(const uint2*)&Bs[k8][wn * NT + nt][lane * 2];
#pragma unroll
            for (int mt = 0; mt < 2; mt++)
#pragma unroll
                for (int nt = 0; nt < NT; nt++)
                    mma_tf32(acc[mt][nt], a[mt], b[nt]);
        }
    }

    const int r = lane >> 2, cc = (lane & 3) * 2;
#pragma unroll
    for (int mt = 0; mt < 2; mt++) {
#pragma unroll
        for (int nt = 0; nt < NT; nt++) {
            int col = c0 + (wn * NT + nt) * 8 + cc;
            float bx = 0.f, by = 0.f;
            if (bias) { bx = bias[col]; by = bias[col + 1]; }
            int row = row0 + (wm * 2 + mt) * 16 + r;
            if (row < M) {
                float v0 = acc[mt][nt][0] + bx, v1 = acc[mt][nt][1] + by;
                if (act == 1) { v0 = elu1(v0); v1 = elu1(v1); }
                *(float2*)(C + (size_t)row * NCOL + col) = make_float2(v0, v1);
            }
            int row2 = row + 8;
            if (row2 < M) {
                float v2 = acc[mt][nt][2] + bx, v3 = acc[mt][nt][3] + by;
                if (act == 1) { v2 = elu1(v2); v3 = elu1(v3); }
                *(float2*)(C + (size_t)row2 * NCOL + col) = make_float2(v2, v3);
            }
        }
    }
}

// ---------------------------------------------------------------------------
// GAT1 alpha per node
// ---------------------------------------------------------------------------
__global__ void alpha1_kernel(const float* __restrict__ a1s, const float* __restrict__ a1d) {
    int gid = blockIdx.x * blockDim.x + threadIdx.x;
    if (gid >= N * 8) return;
    int i = gid >> 3, h = gid & 7;
    const float4* z = (const float4*)(g_z1 + (size_t)i * 64 + h * 8);
    float4 z0 = z[0], z1 = z[1];
    const float4* s4 = (const float4*)(a1s + h * 8);
    const float4* d4 = (const float4*)(a1d + h * 8);
    float4 s0 = s4[0], s1 = s4[1], d0 = d4[0], d1 = d4[1];
    g_as1[gid] = z0.x*s0.x + z0.y*s0.y + z0.z*s0.z + z0.w*s0.w
               + z1.x*s1.x + z1.y*s1.y + z1.z*s1.z + z1.w*s1.w;
    g_ad1[gid] = z0.x*d0.x + z0.y*d0.y + z0.z*d0.z + z0.w*d0.w
               + z1.x*d1.x + z1.y*d1.y + z1.z*d1.z + z1.w*d1.w;
}

// ---------------------------------------------------------------------------
// GAT1 fused: no-max softmax denom + half-warp-per-edge aggregation
// ---------------------------------------------------------------------------
__global__ void gat1_fused(const float* __restrict__ b1) {
    int gid = blockIdx.x * blockDim.x + threadIdx.x;
    int node = gid >> 5, lane = gid & 31;
    if (node >= N) return;
    int beg = g_off[node], deg = g_deg[node];

    float ad[8], asn[8];
    {
        const float4* p = (const float4*)(g_ad1 + (size_t)node * 8);
        float4 a = p[0], b = p[1];
        ad[0]=a.x; ad[1]=a.y; ad[2]=a.z; ad[3]=a.w; ad[4]=b.x; ad[5]=b.y; ad[6]=b.z; ad[7]=b.w;
        const float4* q = (const float4*)(g_as1 + (size_t)node * 8);
        float4 c = q[0], d = q[1];
        asn[0]=c.x; asn[1]=c.y; asn[2]=c.z; asn[3]=c.w; asn[4]=d.x; asn[5]=d.y; asn[6]=d.z; asn[7]=d.w;
    }

    // denom pass (self-loop on lane 0)
    float den[8];
#pragma unroll
    for (int h = 0; h < 8; h++) den[h] = (lane == 0) ? __expf(lrelu(asn[h] + ad[h])) : 0.f;
    for (int k = lane; k < deg; k += 32) {
        int s = g_csr[beg + k];
        const float4* p = (const float4*)(g_as1 + (size_t)s * 8);
        float4 a = p[0], b = p[1];
        float sv[8] = {a.x, a.y, a.z, a.w, b.x, b.y, b.z, b.w};
#pragma unroll
        for (int h = 0; h < 8; h++) den[h] += __expf(lrelu(sv[h] + ad[h]));
    }
#pragma unroll
    for (int o = 16; o; o >>= 1)
#pragma unroll
        for (int h = 0; h < 8; h++) den[h] += __shfl_xor_sync(0xffffffff, den[h], o);

    // aggregation: half-warp per edge; lane covers 4 channels (float4)
    const int half = lane >> 4;
    const int l16  = lane & 15;
    const int c    = l16 * 4;
    const int hh   = l16 >> 1;           // head = c/8
    const float adh = ad[hh];
    const float rh  = 1.f / (den[hh] + 1e-16f);

    float4 acc = make_float4(0.f, 0.f, 0.f, 0.f);
    if (half == 0) {
        float w = __expf(lrelu(asn[hh] + adh)) * rh;
        float4 z = *(const float4*)(g_z1 + (size_t)node * 64 + c);
        acc = make_float4(w*z.x, w*z.y, w*z.z, w*z.w);
    }
    for (int k = half; k < deg; k += 2) {
        int s = g_csr[beg + k];
        float w = __expf(lrelu(g_as1[(size_t)s * 8 + hh] + adh)) * rh;
        float4 z = *(const float4*)(g_z1 + (size_t)s * 64 + c);
        acc.x += w*z.x; acc.y += w*z.y; acc.z += w*z.z; acc.w += w*z.w;
    }
    acc.x += __shfl_xor_sync(0xffffffff, acc.x, 16);
    acc.y += __shfl_xor_sync(0xffffffff, acc.y, 16);
    acc.z += __shfl_xor_sync(0xffffffff, acc.z, 16);
    acc.w += __shfl_xor_sync(0xffffffff, acc.w, 16);
    if (half == 0) {
        float4 bb = *(const float4*)(b1 + c);
        acc.x = elu1(acc.x + bb.x); acc.y = elu1(acc.y + bb.y);
        acc.z = elu1(acc.z + bb.z); acc.w = elu1(acc.w + bb.w);
        *(float4*)(g_h2 + (size_t)node * 64 + c) = acc;
    }
}

// ---------------------------------------------------------------------------
// GAT2 alpha (1 head, 64 ch)
// ---------------------------------------------------------------------------
__global__ void alpha2_kernel(const float* __restrict__ a2s, const float* __restrict__ a2d) {
    int gt = blockIdx.x * blockDim.x + threadIdx.x;
    int w = gt >> 5, lane = gt & 31;
    if (w >= N) return;
    float2 z  = ((const float2*)(g_z2 + (size_t)w * 64))[lane];
    float2 cs = ((const float2*)a2s)[lane];
    float2 cd = ((const float2*)a2d)[lane];
    float vs = z.x * cs.x + z.y * cs.y;
    float vd = z.x * cd.x + z.y * cd.y;
#pragma unroll
    for (int o = 16; o; o >>= 1) {
        vs += __shfl_down_sync(0xffffffff, vs, o);
        vd += __shfl_down_sync(0xffffffff, vd, o);
    }
    if (lane == 0) { g_as2[w] = vs; g_ad2[w] = vd; }
}

// ---------------------------------------------------------------------------
// GAT2 fused: no-max softmax + half-warp-per-edge aggregation
// ---------------------------------------------------------------------------
__global__ void gat2_fused(const float* __restrict__ b2) {
    int gid = blockIdx.x * blockDim.x + threadIdx.x;
    int node = gid >> 5, lane = gid & 31;
    if (node >= N) return;
    int beg = g_off[node], deg = g_deg[node];
    float adn = g_ad2[node], asn = g_as2[node];

    float den = (lane == 0) ? __expf(lrelu(asn + adn)) : 0.f;
    for (int k = lane; k < deg; k += 32)
        den += __expf(lrelu(g_as2[g_csr[beg + k]] + adn));
#pragma unroll
    for (int o = 16; o; o >>= 1) den += __shfl_xor_sync(0xffffffff, den, o);
    float rden = 1.f / (den + 1e-16f);

    const int half = lane >> 4;
    const int c = (lane & 15) * 4;
    float4 acc = make_float4(0.f, 0.f, 0.f, 0.f);
    if (half == 0) {
        float w = __expf(lrelu(asn + adn)) * rden;
        float4 z = *(const float4*)(g_z2 + (size_t)node * 64 + c);
        acc = make_float4(w*z.x, w*z.y, w*z.z, w*z.w);
    }
    for (int k = half; k < deg; k += 2) {
        int s = g_csr[beg + k];
        float w = __expf(lrelu(g_as2[s] + adn)) * rden;
        float4 z = *(const float4*)(g_z2 + (size_t)s * 64 + c);
        acc.x += w*z.x; acc.y += w*z.y; acc.z += w*z.z; acc.w += w*z.w;
    }
    acc.x += __shfl_xor_sync(0xffffffff, acc.x, 16);
    acc.y += __shfl_xor_sync(0xffffffff, acc.y, 16);
    acc.z += __shfl_xor_sync(0xffffffff, acc.z, 16);
    acc.w += __shfl_xor_sync(0xffffffff, acc.w, 16);
    if (half == 0) {
        float4 bb = *(const float4*)(b2 + c);
        *(float4*)(g_h3 + (size_t)node * 64 + c) =
            make_float4(acc.x + bb.x, acc.y + bb.y, acc.z + bb.z, acc.w + bb.w);
    }
}

// ---------------------------------------------------------------------------
// Global mean + head
// ---------------------------------------------------------------------------
__global__ void reduce_final() {
    int t = threadIdx.x;
    int c = t & 63;
    int r0 = blockIdx.x * 4 + (t >> 6);
    float acc = 0.f;
    for (int i = r0; i < N; i += gridDim.x * 4)
        acc += g_h3[(size_t)i * 64 + c];
    atomicAdd(&g_gsum[c], acc);
}

__global__ void final_kernel(const float* __restrict__ Wr, const float* __restrict__ br,
                             float* __restrict__ out) {
    __shared__ float sm[64];
    int t = threadIdx.x;
    sm[t] = g_gsum[t] * (1.0f / (float)N) * Wr[t];
    __syncthreads();
    if (t == 0) {
        float s = 0.f;
        for (int i = 0; i < 64; i++) s += sm[i];
        out[0] = s + br[0];
    }
}

// ---------------------------------------------------------------------------
// Launch
// ---------------------------------------------------------------------------
extern "C" void kernel_launch(void* const* d_in, const int* in_sizes, int n_in,
                              void* d_out, int out_size) {
    const float* x      = (const float*)d_in[0];
    const void*  ei     = d_in[1];
    const float* W_rel  = (const float*)d_in[2];
    const float* b_rel  = (const float*)d_in[3];
    const float* W_root = (const float*)d_in[4];
    const float* W1     = (const float*)d_in[5];
    const float* a1s    = (const float*)d_in[6];
    const float* a1d    = (const float*)d_in[7];
    const float* b1     = (const float*)d_in[8];
    const float* W2     = (const float*)d_in[9];
    const float* a2s    = (const float*)d_in[10];
    const float* a2d    = (const float*)d_in[11];
    const float* b2     = (const float*)d_in[12];
    const float* Wr     = (const float*)d_in[13];
    const float* br     = (const float*)d_in[14];
    float* out          = (float*)d_out;

    float *p_nbr, *p_h, *p_z1, *p_h2, *p_z2;
    cudaGetSymbolAddress((void**)&p_nbr, g_nbr);
    cudaGetSymbolAddress((void**)&p_h,   g_h);
    cudaGetSymbolAddress((void**)&p_z1,  g_z1);
    cudaGetSymbolAddress((void**)&p_h2,  g_h2);
    cudaGetSymbolAddress((void**)&p_z2,  g_z2);

    init_kernel<<<256, 256>>>((const int*)ei);

    hist_kernel<<<(E + 255) / 256, 256>>>(ei);
    scan1_kernel<<<NBLK, SCAN_B>>>();
    scan2_kernel<<<1, 64>>>();
    scan3_kernel<<<NBLK, SCAN_B>>>();
    fill_kernel<<<(E + 255) / 256, 256>>>(ei);

    gather_nbr_kernel<<<(N * 32 + 255) / 256, 256>>>(x);
    {
        dim3 g((N + 127) / 128, 1);
        tf32_linear<128><<<g, 256>>>(p_nbr, W_rel, 128, x, W_root, 128, b_rel, p_h, N, 128, 1);
    }
    {
        dim3 g((N + 127) / 128, 1);
        tf32_linear<64><<<g, 256>>>(p_h, W1, 128, nullptr, nullptr, 0, nullptr, p_z1, N, 64, 0);
    }
    alpha1_kernel<<<(N * 8 + 255) / 256, 256>>>(a1s, a1d);
    gat1_fused<<<(N * 32 + 255) / 256, 256>>>(b1);

    {
        dim3 g((N + 127) / 128, 1);
        tf32_linear<64><<<g, 256>>>(p_h2, W2, 64, nullptr, nullptr, 0, nullptr, p_z2, N, 64, 0);
    }
    alpha2_kernel<<<(N * 32 + 255) / 256, 256>>>(a2s, a2d);
    gat2_fused<<<(N * 32 + 255) / 256, 256>>>(b2);

    reduce_final<<<128, 256>>>();
    final_kernel<<<1, 64>>>(Wr, br, out);
}